// round 4
// baseline (speedup 1.0000x reference)
#include <cuda_runtime.h>

#define T_STEPS 2048
#define BATCH   256
#define HID     64
#define EMBED   128
#define GATES   256

typedef unsigned long long ull;

// Scratch (__device__ globals — allocation-free).
__device__ float g_buf0[(size_t)T_STEPS * BATCH * HID];    // layer0 h sequence
__device__ float g_buf1[(size_t)T_STEPS * BATCH * HID];    // layer1 h sequence
__device__ float g_xg[(size_t)T_STEPS * BATCH * GATES];    // precomputed input gates (reused l1,l2)
__device__ float g_last[BATCH * HID];                      // layer2 last hidden

// ---- packed fp32x2 FMA ----
__device__ __forceinline__ ull ffma2(ull a, ull b, ull c) {
    ull d;
    asm("fma.rn.f32x2 %0, %1, %2, %3;" : "=l"(d) : "l"(a), "l"(b), "l"(c));
    return d;
}
__device__ __forceinline__ float sumhalves(ull v) {
    float lo, hi;
    asm("mov.b64 {%0, %1}, %2;" : "=f"(lo), "=f"(hi) : "l"(v));
    return lo + hi;
}
__device__ __forceinline__ float fast_tanh(float x) {
    float y;
    asm("tanh.approx.f32 %0, %1;" : "=f"(y) : "f"(x));
    return y;
}
__device__ __forceinline__ float fast_sigm(float x) {
    return fmaf(fast_tanh(0.5f * x), 0.5f, 0.5f);
}

// Thread->gate map (rec kernels): warp w, lane l: unit j = w*8 + (l>>2), type = l&3
// (0:i 1:f 2:g 3:o). Weight row gr = type*64 + j. Quad butterfly shuffles deliver
// (i,f,g,o) to the type==0 lane, which owns the c/h update for unit j.

// ============================================================================
// Layer 0 recurrence: input dim = 1. 256 blocks x 256 threads, 1 row/block,
// 2 blocks/SM so the two blocks' tails/dots interleave.
// ============================================================================
__global__ void __launch_bounds__(256, 2) lstm_l0(
    const float* __restrict__ x,
    const float* __restrict__ Wih, const float* __restrict__ Whh,
    const float* __restrict__ bih, const float* __restrict__ bhh)
{
    __shared__ __align__(16) float xs[T_STEPS];        // 8 KB: this row's x
    __shared__ __align__(16) float hs[2][HID];         // [parity][j]

    const int tid = threadIdx.x;
    const int b   = blockIdx.x;

    {   // coalesced float4 stage of x row
        const float4* xr = (const float4*)(x + (size_t)b * T_STEPS);
        float4* xd = (float4*)xs;
        xd[tid]       = xr[tid];
        xd[tid + 256] = xr[tid + 256];
    }

    const int w = tid >> 5, l = tid & 31;
    const int j = (w << 3) | (l >> 2);
    const int type = l & 3;
    const int gr = type * HID + j;

    const float wih  = Wih[gr];
    const float bias = bih[gr] + bhh[gr];

    ull wreg[32];
    const ull* wr = (const ull*)(Whh + gr * HID);
#pragma unroll
    for (int q = 0; q < 32; q++) wreg[q] = wr[q];

    if (tid < HID) hs[0][tid] = 0.f;
    float c = 0.f;
    __syncthreads();

    for (int t = 0; t < T_STEPS; t++) {
        const int cur = t & 1, nxt = cur ^ 1;
        ull a0 = 0ull, a1 = 0ull;
        const double2* H = (const double2*)hs[cur];
#pragma unroll
        for (int q = 0; q < 16; q++) {
            double2 hq = H[q];
            a0 = ffma2(wreg[2*q],   __double_as_longlong(hq.x), a0);
            a1 = ffma2(wreg[2*q+1], __double_as_longlong(hq.y), a1);
        }
        float v = sumhalves(a0) + sumhalves(a1) + fmaf(wih, xs[t], bias);
        v = (type == 2) ? fast_tanh(v) : fast_sigm(v);

        float fv = __shfl_xor_sync(0xffffffffu, v, 1);
        float gv = __shfl_xor_sync(0xffffffffu, v, 2);
        float ov = __shfl_xor_sync(0xffffffffu, fv, 2);

        c = fv * c + v * gv;
        float h = ov * fast_tanh(c);

        if (type == 0) {
            hs[nxt][j] = h;
            g_buf0[((size_t)t * BATCH + b) * HID + j] = h;
        }
        __syncthreads();
    }
}

// ============================================================================
// Input-gate projection (parallel GEMM, no recurrence):
//   g_xg[t][b][g] = bias[g] + sum_k in[t][b][k] * Wih[g][k]     (K = 64)
// SRC 0: in = g_buf0, SRC 1: in = g_buf1. 8192 blocks x 256 threads,
// 64 rows per block staged through smem; thread g holds Wih row in regs.
// ============================================================================
#define PROJ_ROWS 64
template<int SRC>
__global__ void __launch_bounds__(256) proj_kernel(
    const float* __restrict__ Wih,
    const float* __restrict__ bih, const float* __restrict__ bhh)
{
    const float* in = (SRC == 0) ? g_buf0 : g_buf1;
    __shared__ __align__(16) float xt[PROJ_ROWS][HID];   // 16 KB

    const int tid = threadIdx.x;
    const size_t row0 = (size_t)blockIdx.x * PROJ_ROWS;

    {   // coalesced stage: 64 rows x 64 floats = 1024 float4
        const float4* src = (const float4*)(in + row0 * HID);
        float4* dst = (float4*)xt;
#pragma unroll
        for (int i = 0; i < 4; i++) dst[tid + 256 * i] = src[tid + 256 * i];
    }

    const int g = tid;
    const float bias = bih[g] + bhh[g];
    ull wreg[32];
    const ull* wr = (const ull*)(Wih + g * HID);
#pragma unroll
    for (int q = 0; q < 32; q++) wreg[q] = wr[q];
    __syncthreads();

    float* outp = g_xg + row0 * GATES + g;
#pragma unroll 2
    for (int r = 0; r < PROJ_ROWS; r++) {
        ull a0 = 0ull, a1 = 0ull;
        const double2* H = (const double2*)xt[r];
#pragma unroll
        for (int q = 0; q < 16; q++) {
            double2 hq = H[q];
            a0 = ffma2(wreg[2*q],   __double_as_longlong(hq.x), a0);
            a1 = ffma2(wreg[2*q+1], __double_as_longlong(hq.y), a1);
        }
        outp[(size_t)r * GATES] = sumhalves(a0) + sumhalves(a1) + bias;
    }
}

// ============================================================================
// Layers 1/2 recurrence (recurrent half only): gates = g_xg[t] + h @ Whh^T.
// K = 64. 256 blocks x 256 threads, 1 row/block, 2 blocks/SM.
// MODE 1: writes g_buf1 (full sequence). MODE 2: writes g_last only.
// ============================================================================
template<int MODE>
__global__ void __launch_bounds__(256, 2) lstm_rec(
    const float* __restrict__ Whh)
{
    __shared__ __align__(16) float hs[2][HID];

    const int tid = threadIdx.x;
    const int b   = blockIdx.x;

    const int w = tid >> 5, l = tid & 31;
    const int j = (w << 3) | (l >> 2);
    const int type = l & 3;
    const int gr = type * HID + j;

    ull wreg[32];
    const ull* wr = (const ull*)(Whh + gr * HID);
#pragma unroll
    for (int q = 0; q < 32; q++) wreg[q] = wr[q];

    if (tid < HID) hs[0][tid] = 0.f;
    float c = 0.f;

    const float* xg = g_xg + (size_t)b * GATES + gr;
    float pf = xg[0];                                  // xg[t=0][b][gr]
    __syncthreads();

    for (int t = 0; t < T_STEPS; t++) {
        const int cur = t & 1, nxt = cur ^ 1;
        float xg_cur = pf;
        if (t + 1 < T_STEPS)
            pf = xg[(size_t)(t + 1) * BATCH * GATES];  // prefetch under the dot

        ull a0 = 0ull, a1 = 0ull;
        const double2* H = (const double2*)hs[cur];
#pragma unroll
        for (int q = 0; q < 16; q++) {
            double2 hq = H[q];
            a0 = ffma2(wreg[2*q],   __double_as_longlong(hq.x), a0);
            a1 = ffma2(wreg[2*q+1], __double_as_longlong(hq.y), a1);
        }
        float v = sumhalves(a0) + sumhalves(a1) + xg_cur;
        v = (type == 2) ? fast_tanh(v) : fast_sigm(v);

        float fv = __shfl_xor_sync(0xffffffffu, v, 1);
        float gv = __shfl_xor_sync(0xffffffffu, v, 2);
        float ov = __shfl_xor_sync(0xffffffffu, fv, 2);

        c = fv * c + v * gv;
        float h = ov * fast_tanh(c);

        if (type == 0) {
            hs[nxt][j] = h;
            if (MODE == 1) {
                g_buf1[((size_t)t * BATCH + b) * HID + j] = h;
            } else if (t == T_STEPS - 1) {
                g_last[b * HID + j] = h;
            }
        }
        __syncthreads();
    }
}

// ============================================================================
// Final FC:  out[b][e] = g_last[b] . fcW[e] + fcb[e]
// ============================================================================
__global__ void __launch_bounds__(256) fc_kernel(
    const float* __restrict__ W, const float* __restrict__ bvec,
    float* __restrict__ out)
{
    const int idx = blockIdx.x * 256 + threadIdx.x;
    const int b = idx >> 7, e = idx & 127;
    const float4* w4 = (const float4*)(W + e * HID);
    const float4* h4 = (const float4*)(g_last + b * HID);
    float acc = 0.f;
#pragma unroll
    for (int q = 0; q < 16; q++) {
        float4 a = w4[q], h = h4[q];
        acc = fmaf(a.x, h.x, acc);
        acc = fmaf(a.y, h.y, acc);
        acc = fmaf(a.z, h.z, acc);
        acc = fmaf(a.w, h.w, acc);
    }
    out[idx] = acc + bvec[e];
}

// ============================================================================
extern "C" void kernel_launch(void* const* d_in, const int* in_sizes, int n_in,
                              void* d_out, int out_size)
{
    const float* x    = (const float*)d_in[0];
    const float* Wih0 = (const float*)d_in[1];
    const float* Whh0 = (const float*)d_in[2];
    const float* bih0 = (const float*)d_in[3];
    const float* bhh0 = (const float*)d_in[4];
    const float* Wih1 = (const float*)d_in[5];
    const float* Whh1 = (const float*)d_in[6];
    const float* bih1 = (const float*)d_in[7];
    const float* bhh1 = (const float*)d_in[8];
    const float* Wih2 = (const float*)d_in[9];
    const float* Whh2 = (const float*)d_in[10];
    const float* bih2 = (const float*)d_in[11];
    const float* bhh2 = (const float*)d_in[12];
    const float* fcW  = (const float*)d_in[13];
    const float* fcb  = (const float*)d_in[14];

    const int PROJ_GRID = (T_STEPS * BATCH) / PROJ_ROWS;   // 8192

    lstm_l0   <<<BATCH, 256>>>(x, Wih0, Whh0, bih0, bhh0);
    proj_kernel<0><<<PROJ_GRID, 256>>>(Wih1, bih1, bhh1);
    lstm_rec<1><<<BATCH, 256>>>(Whh1);
    proj_kernel<1><<<PROJ_GRID, 256>>>(Wih2, bih2, bhh2);
    lstm_rec<2><<<BATCH, 256>>>(Whh2);
    fc_kernel <<<(BATCH * EMBED) / 256, 256>>>(fcW, fcb, (float*)d_out);
}

// round 6
// speedup vs baseline: 1.1619x; 1.1619x over previous
#include <cuda_runtime.h>

#define T_STEPS 2048
#define BATCH   256
#define HID     64
#define EMBED   128
#define GATES   256

typedef unsigned long long ull;

// Scratch (__device__ globals — allocation-free).
// xg streams: precomputed input-gate activations (bias INCLUDED) for next layer.
__device__ float g_xgA[(size_t)T_STEPS * BATCH * GATES];   // layer0 -> layer1
__device__ float g_xgB[(size_t)T_STEPS * BATCH * GATES];   // layer1 -> layer2
__device__ float g_last[BATCH * HID];                      // layer2 last hidden

// ---- packed fp32x2 FMA ----
__device__ __forceinline__ ull ffma2(ull a, ull b, ull c) {
    ull d;
    asm("fma.rn.f32x2 %0, %1, %2, %3;" : "=l"(d) : "l"(a), "l"(b), "l"(c));
    return d;
}
__device__ __forceinline__ float sumhalves(ull v) {
    float lo, hi;
    asm("mov.b64 {%0, %1}, %2;" : "=f"(lo), "=f"(hi) : "l"(v));
    return lo + hi;
}
__device__ __forceinline__ float fast_tanh(float x) {
    float y;
    asm("tanh.approx.f32 %0, %1;" : "=f"(y) : "f"(x));
    return y;
}
__device__ __forceinline__ float fast_sigm(float x) {
    return fmaf(fast_tanh(0.5f * x), 0.5f, 0.5f);
}

// Thread->gate map: warp w, lane l: unit j = w*8 + (l>>2), type = l&3
// (0:i 1:f 2:g 3:o). Weight row gr = type*64 + j (PyTorch order). Butterfly
// shuffles deliver (i,f,g,o) to the type==0 lane which owns the c/h update.

// ============================================================================
// Fused LSTM layer. 128 blocks x 256 threads, 2 batch rows per block.
//   L=0: input = x (scalar per step) + own bias, proj -> g_xgA (biasN baked in)
//   L=1: input = g_xgA (bias already included), proj -> g_xgB
//   L=2: input = g_xgB (bias already included), writes g_last at t = T-1
// The proj dot (Wih_next[gr] . h[t-1]) shares the smem h loads with the rec
// dot; at step t it produces xg_next[t-1] (h[t-1] lives in hs[cur]).
// ============================================================================
template<int L>
__global__ void __launch_bounds__(256, 1) lstm_layer(
    const float* __restrict__ x,        // L==0 only
    const float* __restrict__ Wih,      // this layer (L==0: column scalar)
    const float* __restrict__ Whh,
    const float* __restrict__ bih, const float* __restrict__ bhh,
    const float* __restrict__ WihN,     // next layer's Wih (L<2)
    const float* __restrict__ bihN, const float* __restrict__ bhhN)
{
    __shared__ __align__(16) float xs[2][(L == 0) ? T_STEPS : 1]; // L0: 16 KB
    __shared__ __align__(16) float hs[2][2][HID];                 // [parity][row][j]

    const int tid = threadIdx.x;
    const int b0  = blockIdx.x * 2;

    if (L == 0) {
        const float4* xr = (const float4*)(x + (size_t)b0 * T_STEPS);
        float4* xd = (float4*)xs;
#pragma unroll
        for (int i = 0; i < 4; i++) xd[tid + 256 * i] = xr[tid + 256 * i];
    }

    const int w = tid >> 5, l = tid & 31;
    const int j = (w << 3) | (l >> 2);
    const int type = l & 3;
    const int gr = type * HID + j;

    const float wih0  = (L == 0) ? Wih[gr] : 0.f;
    const float bias  = (L == 0) ? (bih[gr] + bhh[gr]) : 0.f;  // L>=1: bias is in xg stream
    const float biasN = (L < 2) ? (bihN[gr] + bhhN[gr]) : 0.f;

    ull wrec[32];
    {
        const ull* wr = (const ull*)(Whh + gr * HID);
#pragma unroll
        for (int q = 0; q < 32; q++) wrec[q] = wr[q];
    }
    ull wproj[(L < 2) ? 32 : 1];
    if (L < 2) {
        const ull* wp = (const ull*)(WihN + gr * HID);
#pragma unroll
        for (int q = 0; q < 32; q++) wproj[q] = wp[q];
    }

    if (tid < 128) hs[0][tid >> 6][tid & 63] = 0.f;
    float c0 = 0.f, c1 = 0.f;

    const float* xg_in = (L == 1) ? g_xgA : g_xgB;   // L==0 unused
    float pf0 = 0.f, pf1 = 0.f;
    if (L >= 1) {
        pf0 = xg_in[(size_t)b0 * GATES + gr];
        pf1 = xg_in[(size_t)(b0 + 1) * GATES + gr];
    }
    float* xg_out = (L == 0) ? g_xgA : g_xgB;        // L==2 unused

    __syncthreads();

    for (int t = 0; t < T_STEPS; t++) {
        const int cur = t & 1, nxt = cur ^ 1;

        float in0, in1;
        if (L == 0) {
            in0 = fmaf(wih0, xs[0][t], bias);
            in1 = fmaf(wih0, xs[1][t], bias);
        } else {
            in0 = pf0;                        // bias already baked in by producer
            in1 = pf1;
            if (t + 1 < T_STEPS) {            // prefetch next step's xg under the dot
                pf0 = xg_in[((size_t)(t + 1) * BATCH + b0) * GATES + gr];
                pf1 = xg_in[((size_t)(t + 1) * BATCH + b0 + 1) * GATES + gr];
            }
        }

        ull r0a = 0ull, r0b = 0ull, r1a = 0ull, r1b = 0ull;   // rec accs
        ull p0a = 0ull, p0b = 0ull, p1a = 0ull, p1b = 0ull;   // proj accs
        const double2* H0 = (const double2*)hs[cur][0];
        const double2* H1 = (const double2*)hs[cur][1];
#pragma unroll
        for (int q = 0; q < 16; q++) {
            double2 ha = H0[q];                 // LDS.128: 4 h floats, row 0
            double2 hb = H1[q];                 // row 1
            ull hax = __double_as_longlong(ha.x), hay = __double_as_longlong(ha.y);
            ull hbx = __double_as_longlong(hb.x), hby = __double_as_longlong(hb.y);
            r0a = ffma2(wrec[2*q],   hax, r0a);
            r0b = ffma2(wrec[2*q+1], hay, r0b);
            r1a = ffma2(wrec[2*q],   hbx, r1a);
            r1b = ffma2(wrec[2*q+1], hby, r1b);
            if (L < 2) {
                p0a = ffma2(wproj[2*q],   hax, p0a);
                p0b = ffma2(wproj[2*q+1], hay, p0b);
                p1a = ffma2(wproj[2*q],   hbx, p1a);
                p1b = ffma2(wproj[2*q+1], hby, p1b);
            }
        }

        // proj result = xg_next[t-1]  (h[t-1] is what we just read)
        if (L < 2 && t >= 1) {
            float xp0 = sumhalves(p0a) + sumhalves(p0b) + biasN;
            float xp1 = sumhalves(p1a) + sumhalves(p1b) + biasN;
            xg_out[((size_t)(t - 1) * BATCH + b0) * GATES + gr]     = xp0;
            xg_out[((size_t)(t - 1) * BATCH + b0 + 1) * GATES + gr] = xp1;
        }

        float v0 = sumhalves(r0a) + sumhalves(r0b) + in0;
        float v1 = sumhalves(r1a) + sumhalves(r1b) + in1;
        if (type == 2) { v0 = fast_tanh(v0); v1 = fast_tanh(v1); }
        else           { v0 = fast_sigm(v0); v1 = fast_sigm(v1); }

        float f0 = __shfl_xor_sync(0xffffffffu, v0, 1);
        float g0 = __shfl_xor_sync(0xffffffffu, v0, 2);
        float o0 = __shfl_xor_sync(0xffffffffu, f0, 2);
        float f1 = __shfl_xor_sync(0xffffffffu, v1, 1);
        float g1 = __shfl_xor_sync(0xffffffffu, v1, 2);
        float o1 = __shfl_xor_sync(0xffffffffu, f1, 2);

        c0 = f0 * c0 + v0 * g0;
        c1 = f1 * c1 + v1 * g1;
        float h0 = o0 * fast_tanh(c0);
        float h1 = o1 * fast_tanh(c1);

        if (type == 0) {
            hs[nxt][0][j] = h0;
            hs[nxt][1][j] = h1;
            if (L == 2 && t == T_STEPS - 1) {
                g_last[b0 * HID + j]       = h0;
                g_last[(b0 + 1) * HID + j] = h1;
            }
        }
        __syncthreads();
    }

    // Final proj: xg_next[T-1] from h[T-1] (in hs[0] since T is even).
    if (L < 2) {
        ull p0a = 0ull, p0b = 0ull, p1a = 0ull, p1b = 0ull;
        const double2* H0 = (const double2*)hs[0][0];
        const double2* H1 = (const double2*)hs[0][1];
#pragma unroll
        for (int q = 0; q < 16; q++) {
            double2 ha = H0[q];
            double2 hb = H1[q];
            p0a = ffma2(wproj[2*q],   __double_as_longlong(ha.x), p0a);
            p0b = ffma2(wproj[2*q+1], __double_as_longlong(ha.y), p0b);
            p1a = ffma2(wproj[2*q],   __double_as_longlong(hb.x), p1a);
            p1b = ffma2(wproj[2*q+1], __double_as_longlong(hb.y), p1b);
        }
        float xp0 = sumhalves(p0a) + sumhalves(p0b) + biasN;
        float xp1 = sumhalves(p1a) + sumhalves(p1b) + biasN;
        float* xg_out2 = (L == 0) ? g_xgA : g_xgB;
        xg_out2[((size_t)(T_STEPS - 1) * BATCH + b0) * GATES + gr]     = xp0;
        xg_out2[((size_t)(T_STEPS - 1) * BATCH + b0 + 1) * GATES + gr] = xp1;
    }
}

// ============================================================================
// Final FC:  out[b][e] = g_last[b] . fcW[e] + fcb[e]
// ============================================================================
__global__ void __launch_bounds__(256) fc_kernel(
    const float* __restrict__ W, const float* __restrict__ bvec,
    float* __restrict__ out)
{
    const int idx = blockIdx.x * 256 + threadIdx.x;
    const int b = idx >> 7, e = idx & 127;
    const float4* w4 = (const float4*)(W + e * HID);
    const float4* h4 = (const float4*)(g_last + b * HID);
    float acc = 0.f;
#pragma unroll
    for (int q = 0; q < 16; q++) {
        float4 a = w4[q], h = h4[q];
        acc = fmaf(a.x, h.x, acc);
        acc = fmaf(a.y, h.y, acc);
        acc = fmaf(a.z, h.z, acc);
        acc = fmaf(a.w, h.w, acc);
    }
    out[idx] = acc + bvec[e];
}

// ============================================================================
extern "C" void kernel_launch(void* const* d_in, const int* in_sizes, int n_in,
                              void* d_out, int out_size)
{
    const float* x    = (const float*)d_in[0];
    const float* Wih0 = (const float*)d_in[1];
    const float* Whh0 = (const float*)d_in[2];
    const float* bih0 = (const float*)d_in[3];
    const float* bhh0 = (const float*)d_in[4];
    const float* Wih1 = (const float*)d_in[5];
    const float* Whh1 = (const float*)d_in[6];
    const float* bih1 = (const float*)d_in[7];
    const float* bhh1 = (const float*)d_in[8];
    const float* Wih2 = (const float*)d_in[9];
    const float* Whh2 = (const float*)d_in[10];
    const float* bih2 = (const float*)d_in[11];
    const float* bhh2 = (const float*)d_in[12];
    const float* fcW  = (const float*)d_in[13];
    const float* fcb  = (const float*)d_in[14];

    lstm_layer<0><<<BATCH / 2, 256>>>(x,       Wih0, Whh0, bih0, bhh0, Wih1, bih1, bhh1);
    lstm_layer<1><<<BATCH / 2, 256>>>(nullptr, Wih1, Whh1, bih1, bhh1, Wih2, bih2, bhh2);
    lstm_layer<2><<<BATCH / 2, 256>>>(nullptr, Wih2, Whh2, bih2, bhh2, nullptr, nullptr, nullptr);
    fc_kernel<<<(BATCH * EMBED) / 256, 256>>>(fcW, fcb, (float*)d_out);
}

// round 7
// speedup vs baseline: 1.2195x; 1.0495x over previous
#include <cuda_runtime.h>
#include <cuda_fp16.h>

#define T_STEPS 2048
#define BATCH   256
#define HID     64
#define EMBED   128
#define GATES   256

// Scratch (__device__ globals — allocation-free).
// xg streams: precomputed input-gate activations (bias INCLUDED) for next layer.
__device__ float g_xgA[(size_t)T_STEPS * BATCH * GATES];   // layer0 -> layer1
__device__ float g_xgB[(size_t)T_STEPS * BATCH * GATES];   // layer1 -> layer2
__device__ float g_last[BATCH * HID];                      // layer2 last hidden

__device__ __forceinline__ float fast_tanh(float x) {
    float y;
    asm("tanh.approx.f32 %0, %1;" : "=f"(y) : "f"(x));
    return y;
}
__device__ __forceinline__ float fast_sigm(float x) {
    return fmaf(fast_tanh(0.5f * x), 0.5f, 0.5f);
}
__device__ __forceinline__ __half2 u2h2(unsigned int u) {
    return *reinterpret_cast<__half2*>(&u);
}

// Thread->gate map: warp w, lane l: unit j = w*8 + (l>>2), type = l&3
// (0:i 1:f 2:g 3:o). Weight row gr = type*64 + j (PyTorch order). Butterfly
// shuffles deliver (i,f,g,o) to the type==0 lane which owns the c/h update.
//
// Precision scheme: dot products (rec + proj) in fp16 (HFMA2, 4 accumulators
// x 8-deep chains per dot); gate math, c-state, h, xg streams all fp32.
// h is stored in smem as packed half2 (pairs j, j+1) by quad-leader lanes.

// ============================================================================
// Fused LSTM layer. 128 blocks x 256 threads, 2 batch rows per block.
//   L=0: input = x (scalar per step) + own bias, proj -> g_xgA (biasN baked in)
//   L=1: input = g_xgA (bias already included), proj -> g_xgB
//   L=2: input = g_xgB (bias already included), writes g_last at t = T-1
// The proj dot (Wih_next[gr] . h[t-1]) shares the smem h loads with the rec
// dot; at step t it produces xg_next[t-1] (h[t-1] lives in hs2[cur]).
// ============================================================================
template<int L>
__global__ void __launch_bounds__(256, 1) lstm_layer(
    const float* __restrict__ x,        // L==0 only
    const float* __restrict__ Wih,      // this layer (L==0: column scalar)
    const float* __restrict__ Whh,
    const float* __restrict__ bih, const float* __restrict__ bhh,
    const float* __restrict__ WihN,     // next layer's Wih (L<2)
    const float* __restrict__ bihN, const float* __restrict__ bhhN)
{
    __shared__ __align__(16) float   xs[2][(L == 0) ? T_STEPS : 1]; // L0: 16 KB
    __shared__ __align__(16) __half2 hs2[2][2][HID / 2];            // [parity][row][pair]

    const int tid = threadIdx.x;
    const int b0  = blockIdx.x * 2;

    if (L == 0) {
        const float4* xr = (const float4*)(x + (size_t)b0 * T_STEPS);
        float4* xd = (float4*)xs;
#pragma unroll
        for (int i = 0; i < 4; i++) xd[tid + 256 * i] = xr[tid + 256 * i];
    }

    const int w = tid >> 5, l = tid & 31;
    const int j = (w << 3) | (l >> 2);
    const int type = l & 3;
    const int gr = type * HID + j;

    const float wih0  = (L == 0) ? Wih[gr] : 0.f;
    const float bias  = (L == 0) ? (bih[gr] + bhh[gr]) : 0.f;  // L>=1: bias in xg stream
    const float biasN = (L < 2) ? (bihN[gr] + bhhN[gr]) : 0.f;

    // Weights converted to half2 pairs (k, k+1).
    __half2 wrec[32];
    {
        const float2* wr = (const float2*)(Whh + gr * HID);
#pragma unroll
        for (int q = 0; q < 32; q++) wrec[q] = __float22half2_rn(wr[q]);
    }
    __half2 wproj[(L < 2) ? 32 : 1];
    if (L < 2) {
        const float2* wp = (const float2*)(WihN + gr * HID);
#pragma unroll
        for (int q = 0; q < 32; q++) wproj[q] = __float22half2_rn(wp[q]);
    }

    if (tid < 64) hs2[0][tid >> 5][tid & 31] = __float2half2_rn(0.f);
    float c0 = 0.f, c1 = 0.f;

    const float* xg_in = (L == 1) ? g_xgA : g_xgB;   // L==0 unused
    float pf0 = 0.f, pf1 = 0.f;
    if (L >= 1) {
        pf0 = xg_in[(size_t)b0 * GATES + gr];
        pf1 = xg_in[(size_t)(b0 + 1) * GATES + gr];
    }
    float* xg_out = (L == 0) ? g_xgA : g_xgB;        // L==2 unused

    __syncthreads();

    for (int t = 0; t < T_STEPS; t++) {
        const int cur = t & 1, nxt = cur ^ 1;

        float in0, in1;
        if (L == 0) {
            in0 = fmaf(wih0, xs[0][t], bias);
            in1 = fmaf(wih0, xs[1][t], bias);
        } else {
            in0 = pf0;                        // bias baked in by producer
            in1 = pf1;
            if (t + 1 < T_STEPS) {            // prefetch next xg under the dot
                pf0 = xg_in[((size_t)(t + 1) * BATCH + b0) * GATES + gr];
                pf1 = xg_in[((size_t)(t + 1) * BATCH + b0 + 1) * GATES + gr];
            }
        }

        // fp16 dots: 4 accumulators per dot, 8-deep chains.
        __half2 r0[4], r1[4], p0[4], p1[4];
#pragma unroll
        for (int i = 0; i < 4; i++) {
            r0[i] = __float2half2_rn(0.f); r1[i] = __float2half2_rn(0.f);
            if (L < 2) { p0[i] = __float2half2_rn(0.f); p1[i] = __float2half2_rn(0.f); }
        }
        const uint4* H0 = (const uint4*)hs2[cur][0];
        const uint4* H1 = (const uint4*)hs2[cur][1];
#pragma unroll
        for (int q = 0; q < 8; q++) {
            uint4 ha = H0[q];                  // 8 h values (4 half2), row 0
            uint4 hb = H1[q];                  // row 1
            __half2 a0 = u2h2(ha.x), a1 = u2h2(ha.y), a2 = u2h2(ha.z), a3 = u2h2(ha.w);
            __half2 b0h = u2h2(hb.x), b1h = u2h2(hb.y), b2h = u2h2(hb.z), b3h = u2h2(hb.w);
            r0[0] = __hfma2(wrec[4*q+0], a0, r0[0]);
            r0[1] = __hfma2(wrec[4*q+1], a1, r0[1]);
            r0[2] = __hfma2(wrec[4*q+2], a2, r0[2]);
            r0[3] = __hfma2(wrec[4*q+3], a3, r0[3]);
            r1[0] = __hfma2(wrec[4*q+0], b0h, r1[0]);
            r1[1] = __hfma2(wrec[4*q+1], b1h, r1[1]);
            r1[2] = __hfma2(wrec[4*q+2], b2h, r1[2]);
            r1[3] = __hfma2(wrec[4*q+3], b3h, r1[3]);
            if (L < 2) {
                p0[0] = __hfma2(wproj[4*q+0], a0, p0[0]);
                p0[1] = __hfma2(wproj[4*q+1], a1, p0[1]);
                p0[2] = __hfma2(wproj[4*q+2], a2, p0[2]);
                p0[3] = __hfma2(wproj[4*q+3], a3, p0[3]);
                p1[0] = __hfma2(wproj[4*q+0], b0h, p1[0]);
                p1[1] = __hfma2(wproj[4*q+1], b1h, p1[1]);
                p1[2] = __hfma2(wproj[4*q+2], b2h, p1[2]);
                p1[3] = __hfma2(wproj[4*q+3], b3h, p1[3]);
            }
        }

        // Reduce accumulators in fp32.
        float2 s;
        float v0 = in0, v1 = in1;
#pragma unroll
        for (int i = 0; i < 4; i++) {
            s = __half22float2(r0[i]); v0 += s.x + s.y;
            s = __half22float2(r1[i]); v1 += s.x + s.y;
        }

        // proj result = xg_next[t-1]  (h[t-1] is what we just read)
        if (L < 2 && t >= 1) {
            float xp0 = biasN, xp1 = biasN;
#pragma unroll
            for (int i = 0; i < 4; i++) {
                s = __half22float2(p0[i]); xp0 += s.x + s.y;
                s = __half22float2(p1[i]); xp1 += s.x + s.y;
            }
            xg_out[((size_t)(t - 1) * BATCH + b0) * GATES + gr]     = xp0;
            xg_out[((size_t)(t - 1) * BATCH + b0 + 1) * GATES + gr] = xp1;
        }

        if (type == 2) { v0 = fast_tanh(v0); v1 = fast_tanh(v1); }
        else           { v0 = fast_sigm(v0); v1 = fast_sigm(v1); }

        float f0 = __shfl_xor_sync(0xffffffffu, v0, 1);
        float g0 = __shfl_xor_sync(0xffffffffu, v0, 2);
        float o0 = __shfl_xor_sync(0xffffffffu, f0, 2);
        float f1 = __shfl_xor_sync(0xffffffffu, v1, 1);
        float g1 = __shfl_xor_sync(0xffffffffu, v1, 2);
        float o1 = __shfl_xor_sync(0xffffffffu, f1, 2);

        c0 = f0 * c0 + v0 * g0;
        c1 = f1 * c1 + v1 * g1;
        float h0 = o0 * fast_tanh(c0);
        float h1 = o1 * fast_tanh(c1);

        // h_{j+1} comes from the type-0 lane 4 lanes down; even-j quad leaders
        // pack (h_j, h_{j+1}) into one half2 store.
        float hn0 = __shfl_down_sync(0xffffffffu, h0, 4);
        float hn1 = __shfl_down_sync(0xffffffffu, h1, 4);
        if (type == 0 && (j & 1) == 0) {
            hs2[nxt][0][j >> 1] = __floats2half2_rn(h0, hn0);
            hs2[nxt][1][j >> 1] = __floats2half2_rn(h1, hn1);
        }
        if (L == 2 && type == 0 && t == T_STEPS - 1) {
            g_last[b0 * HID + j]       = h0;
            g_last[(b0 + 1) * HID + j] = h1;
        }
        __syncthreads();
    }

    // Final proj: xg_next[T-1] from h[T-1] (in hs2[0] since T is even).
    if (L < 2) {
        __half2 p0[4], p1[4];
#pragma unroll
        for (int i = 0; i < 4; i++) {
            p0[i] = __float2half2_rn(0.f); p1[i] = __float2half2_rn(0.f);
        }
        const uint4* H0 = (const uint4*)hs2[0][0];
        const uint4* H1 = (const uint4*)hs2[0][1];
#pragma unroll
        for (int q = 0; q < 8; q++) {
            uint4 ha = H0[q];
            uint4 hb = H1[q];
            p0[0] = __hfma2(wproj[4*q+0], u2h2(ha.x), p0[0]);
            p0[1] = __hfma2(wproj[4*q+1], u2h2(ha.y), p0[1]);
            p0[2] = __hfma2(wproj[4*q+2], u2h2(ha.z), p0[2]);
            p0[3] = __hfma2(wproj[4*q+3], u2h2(ha.w), p0[3]);
            p1[0] = __hfma2(wproj[4*q+0], u2h2(hb.x), p1[0]);
            p1[1] = __hfma2(wproj[4*q+1], u2h2(hb.y), p1[1]);
            p1[2] = __hfma2(wproj[4*q+2], u2h2(hb.z), p1[2]);
            p1[3] = __hfma2(wproj[4*q+3], u2h2(hb.w), p1[3]);
        }
        float xp0 = biasN, xp1 = biasN;
        float2 s;
#pragma unroll
        for (int i = 0; i < 4; i++) {
            s = __half22float2(p0[i]); xp0 += s.x + s.y;
            s = __half22float2(p1[i]); xp1 += s.x + s.y;
        }
        float* xg_out2 = (L == 0) ? g_xgA : g_xgB;
        xg_out2[((size_t)(T_STEPS - 1) * BATCH + b0) * GATES + gr]     = xp0;
        xg_out2[((size_t)(T_STEPS - 1) * BATCH + b0 + 1) * GATES + gr] = xp1;
    }
}

// ============================================================================
// Final FC:  out[b][e] = g_last[b] . fcW[e] + fcb[e]    (fp32)
// ============================================================================
__global__ void __launch_bounds__(256) fc_kernel(
    const float* __restrict__ W, const float* __restrict__ bvec,
    float* __restrict__ out)
{
    const int idx = blockIdx.x * 256 + threadIdx.x;
    const int b = idx >> 7, e = idx & 127;
    const float4* w4 = (const float4*)(W + e * HID);
    const float4* h4 = (const float4*)(g_last + b * HID);
    float acc = 0.f;
#pragma unroll
    for (int q = 0; q < 16; q++) {
        float4 a = w4[q], h = h4[q];
        acc = fmaf(a.x, h.x, acc);
        acc = fmaf(a.y, h.y, acc);
        acc = fmaf(a.z, h.z, acc);
        acc = fmaf(a.w, h.w, acc);
    }
    out[idx] = acc + bvec[e];
}

// ============================================================================
extern "C" void kernel_launch(void* const* d_in, const int* in_sizes, int n_in,
                              void* d_out, int out_size)
{
    const float* x    = (const float*)d_in[0];
    const float* Wih0 = (const float*)d_in[1];
    const float* Whh0 = (const float*)d_in[2];
    const float* bih0 = (const float*)d_in[3];
    const float* bhh0 = (const float*)d_in[4];
    const float* Wih1 = (const float*)d_in[5];
    const float* Whh1 = (const float*)d_in[6];
    const float* bih1 = (const float*)d_in[7];
    const float* bhh1 = (const float*)d_in[8];
    const float* Wih2 = (const float*)d_in[9];
    const float* Whh2 = (const float*)d_in[10];
    const float* bih2 = (const float*)d_in[11];
    const float* bhh2 = (const float*)d_in[12];
    const float* fcW  = (const float*)d_in[13];
    const float* fcb  = (const float*)d_in[14];

    lstm_layer<0><<<BATCH / 2, 256>>>(x,       Wih0, Whh0, bih0, bhh0, Wih1, bih1, bhh1);
    lstm_layer<1><<<BATCH / 2, 256>>>(nullptr, Wih1, Whh1, bih1, bhh1, Wih2, bih2, bhh2);
    lstm_layer<2><<<BATCH / 2, 256>>>(nullptr, Wih2, Whh2, bih2, bhh2, nullptr, nullptr, nullptr);
    fc_kernel<<<(BATCH * EMBED) / 256, 256>>>(fcW, fcb, (float*)d_out);
}

// round 8
// speedup vs baseline: 1.9787x; 1.6226x over previous
#include <cuda_runtime.h>
#include <cuda_fp16.h>

#define T_STEPS 2048
#define BATCH   256
#define HID     64
#define EMBED   128

__device__ __forceinline__ float fast_tanh(float x) {
    float y;
    asm("tanh.approx.f32 %0, %1;" : "=f"(y) : "f"(x));
    return y;
}
__device__ __forceinline__ float fast_sigm(float x) {
    return fmaf(fast_tanh(0.5f * x), 0.5f, 0.5f);
}
__device__ __forceinline__ __half2 u2h2(unsigned int u) {
    return *reinterpret_cast<__half2*>(&u);
}

// Thread->gate map: warp w, lane l: unit j = w*8 + (l>>2), type = l&3
// (0:i 1:f 2:g 3:o). Weight row gr = type*64 + j (PyTorch order). Butterfly
// shuffles deliver (i,f,g,o) to the type==0 lane which owns the c/h update.
//
// Diagonal pipeline: superstep s computes l0[t=s], l1[t=s-1], l2[t=s-2].
// All reads from hs2[cur] (written at superstep s-1); writes to hs2[nxt];
// one barrier per superstep. Dots run unguarded (bounded garbage when a
// layer is inactive); only guarded tails commit c/h state.

// Per-layer tail: reduce accs, nonlinearity, quad shuffle-exchange, c/h
// update, pack h as half2 into hs2[nxt][LYR].
#define LSTM_TAIL(LYR, ACC0, ACC1, IN0, IN1, Cr0, Cr1, H0OUT, H1OUT)          \
    {                                                                          \
        float v0 = (IN0), v1 = (IN1);                                          \
        float2 s2_;                                                            \
        _Pragma("unroll")                                                      \
        for (int i_ = 0; i_ < 4; i_++) {                                       \
            s2_ = __half22float2(ACC0[i_]); v0 += s2_.x + s2_.y;               \
            s2_ = __half22float2(ACC1[i_]); v1 += s2_.x + s2_.y;               \
        }                                                                      \
        if (type == 2) { v0 = fast_tanh(v0); v1 = fast_tanh(v1); }             \
        else           { v0 = fast_sigm(v0); v1 = fast_sigm(v1); }             \
        float f0 = __shfl_xor_sync(0xffffffffu, v0, 1);                        \
        float g0 = __shfl_xor_sync(0xffffffffu, v0, 2);                        \
        float o0 = __shfl_xor_sync(0xffffffffu, f0, 2);                        \
        float f1 = __shfl_xor_sync(0xffffffffu, v1, 1);                        \
        float g1 = __shfl_xor_sync(0xffffffffu, v1, 2);                        \
        float o1 = __shfl_xor_sync(0xffffffffu, f1, 2);                        \
        Cr0 = f0 * Cr0 + v0 * g0;                                              \
        Cr1 = f1 * Cr1 + v1 * g1;                                              \
        float h0_ = o0 * fast_tanh(Cr0);                                       \
        float h1_ = o1 * fast_tanh(Cr1);                                       \
        float hn0_ = __shfl_down_sync(0xffffffffu, h0_, 4);                    \
        float hn1_ = __shfl_down_sync(0xffffffffu, h1_, 4);                    \
        if (type == 0 && (j & 1) == 0) {                                       \
            hs2[nxt][LYR][0][j >> 1] = __floats2half2_rn(h0_, hn0_);           \
            hs2[nxt][LYR][1][j >> 1] = __floats2half2_rn(h1_, hn1_);           \
        }                                                                      \
        H0OUT = h0_; H1OUT = h1_;                                              \
    }

__global__ void __launch_bounds__(256, 1) lstm_all(
    const float* __restrict__ x,
    const float* __restrict__ Wih0, const float* __restrict__ Whh0,
    const float* __restrict__ bih0, const float* __restrict__ bhh0,
    const float* __restrict__ Wih1, const float* __restrict__ Whh1,
    const float* __restrict__ bih1, const float* __restrict__ bhh1,
    const float* __restrict__ Wih2, const float* __restrict__ Whh2,
    const float* __restrict__ bih2, const float* __restrict__ bhh2,
    const float* __restrict__ fcW,  const float* __restrict__ fcb,
    float* __restrict__ out)
{
    __shared__ __align__(16) float   xs[2][T_STEPS];          // 16 KB
    __shared__ __align__(16) __half2 hs2[2][3][2][HID / 2];   // [par][layer][row][pair]
    __shared__ __align__(16) float   h2last[2][HID];          // final layer2 h (fp32)

    const int tid = threadIdx.x;
    const int b0  = blockIdx.x * 2;

    {   // stage x rows (coalesced float4)
        const float4* xr = (const float4*)(x + (size_t)b0 * T_STEPS);
        float4* xd = (float4*)xs;
#pragma unroll
        for (int i = 0; i < 4; i++) xd[tid + 256 * i] = xr[tid + 256 * i];
    }

    const int w = tid >> 5, l = tid & 31;
    const int j = (w << 3) | (l >> 2);
    const int type = l & 3;
    const int gr = type * HID + j;

    const float wih0v = Wih0[gr];
    const float bias0 = bih0[gr] + bhh0[gr];
    const float bias1 = bih1[gr] + bhh1[gr];
    const float bias2 = bih2[gr] + bhh2[gr];

    // Weights as half2 (k, k+1) pairs: 5 x 32 regs.
    __half2 w0r[32], w1i[32], w1r[32], w2i[32], w2r[32];
    {
        const float2* p0 = (const float2*)(Whh0 + gr * HID);
        const float2* p1 = (const float2*)(Wih1 + gr * HID);
        const float2* p2 = (const float2*)(Whh1 + gr * HID);
        const float2* p3 = (const float2*)(Wih2 + gr * HID);
        const float2* p4 = (const float2*)(Whh2 + gr * HID);
#pragma unroll
        for (int q = 0; q < 32; q++) {
            w0r[q] = __float22half2_rn(p0[q]);
            w1i[q] = __float22half2_rn(p1[q]);
            w1r[q] = __float22half2_rn(p2[q]);
            w2i[q] = __float22half2_rn(p3[q]);
            w2r[q] = __float22half2_rn(p4[q]);
        }
    }

    // Zero both parities of all layer states (bounded reads for inactive layers).
    {
        __half2* hp = (__half2*)hs2;
        for (int i = tid; i < 2 * 3 * 2 * (HID / 2); i += 256)
            hp[i] = __float2half2_rn(0.f);
    }
    float c00 = 0.f, c01 = 0.f, c10 = 0.f, c11 = 0.f, c20 = 0.f, c21 = 0.f;
    __syncthreads();

    for (int s = 0; s < T_STEPS + 2; s++) {
        const int cur = s & 1, nxt = cur ^ 1;

        __half2 A0[4], A1[4], B0[4], B1[4], C0[4], C1[4];
#pragma unroll
        for (int i = 0; i < 4; i++) {
            A0[i] = __float2half2_rn(0.f); A1[i] = __float2half2_rn(0.f);
            B0[i] = __float2half2_rn(0.f); B1[i] = __float2half2_rn(0.f);
            C0[i] = __float2half2_rn(0.f); C1[i] = __float2half2_rn(0.f);
        }

        const uint4* P00 = (const uint4*)hs2[cur][0][0];
        const uint4* P01 = (const uint4*)hs2[cur][0][1];
        const uint4* P10 = (const uint4*)hs2[cur][1][0];
        const uint4* P11 = (const uint4*)hs2[cur][1][1];
        const uint4* P20 = (const uint4*)hs2[cur][2][0];
        const uint4* P21 = (const uint4*)hs2[cur][2][1];

        // Phase 1: h0[cur] feeds l0 rec (A) and l1 input (B).
#pragma unroll
        for (int q = 0; q < 8; q++) {
            uint4 ha = P00[q], hb = P01[q];
            __half2 a0 = u2h2(ha.x), a1 = u2h2(ha.y), a2 = u2h2(ha.z), a3 = u2h2(ha.w);
            __half2 e0 = u2h2(hb.x), e1 = u2h2(hb.y), e2 = u2h2(hb.z), e3 = u2h2(hb.w);
            A0[0] = __hfma2(w0r[4*q+0], a0, A0[0]);
            A0[1] = __hfma2(w0r[4*q+1], a1, A0[1]);
            A0[2] = __hfma2(w0r[4*q+2], a2, A0[2]);
            A0[3] = __hfma2(w0r[4*q+3], a3, A0[3]);
            A1[0] = __hfma2(w0r[4*q+0], e0, A1[0]);
            A1[1] = __hfma2(w0r[4*q+1], e1, A1[1]);
            A1[2] = __hfma2(w0r[4*q+2], e2, A1[2]);
            A1[3] = __hfma2(w0r[4*q+3], e3, A1[3]);
            B0[0] = __hfma2(w1i[4*q+0], a0, B0[0]);
            B0[1] = __hfma2(w1i[4*q+1], a1, B0[1]);
            B0[2] = __hfma2(w1i[4*q+2], a2, B0[2]);
            B0[3] = __hfma2(w1i[4*q+3], a3, B0[3]);
            B1[0] = __hfma2(w1i[4*q+0], e0, B1[0]);
            B1[1] = __hfma2(w1i[4*q+1], e1, B1[1]);
            B1[2] = __hfma2(w1i[4*q+2], e2, B1[2]);
            B1[3] = __hfma2(w1i[4*q+3], e3, B1[3]);
        }
        // Phase 2: h1[cur] feeds l1 rec (B) and l2 input (C).
#pragma unroll
        for (int q = 0; q < 8; q++) {
            uint4 ha = P10[q], hb = P11[q];
            __half2 a0 = u2h2(ha.x), a1 = u2h2(ha.y), a2 = u2h2(ha.z), a3 = u2h2(ha.w);
            __half2 e0 = u2h2(hb.x), e1 = u2h2(hb.y), e2 = u2h2(hb.z), e3 = u2h2(hb.w);
            B0[0] = __hfma2(w1r[4*q+0], a0, B0[0]);
            B0[1] = __hfma2(w1r[4*q+1], a1, B0[1]);
            B0[2] = __hfma2(w1r[4*q+2], a2, B0[2]);
            B0[3] = __hfma2(w1r[4*q+3], a3, B0[3]);
            B1[0] = __hfma2(w1r[4*q+0], e0, B1[0]);
            B1[1] = __hfma2(w1r[4*q+1], e1, B1[1]);
            B1[2] = __hfma2(w1r[4*q+2], e2, B1[2]);
            B1[3] = __hfma2(w1r[4*q+3], e3, B1[3]);
            C0[0] = __hfma2(w2i[4*q+0], a0, C0[0]);
            C0[1] = __hfma2(w2i[4*q+1], a1, C0[1]);
            C0[2] = __hfma2(w2i[4*q+2], a2, C0[2]);
            C0[3] = __hfma2(w2i[4*q+3], a3, C0[3]);
            C1[0] = __hfma2(w2i[4*q+0], e0, C1[0]);
            C1[1] = __hfma2(w2i[4*q+1], e1, C1[1]);
            C1[2] = __hfma2(w2i[4*q+2], e2, C1[2]);
            C1[3] = __hfma2(w2i[4*q+3], e3, C1[3]);
        }
        // Phase 3: h2[cur] feeds l2 rec (C).
#pragma unroll
        for (int q = 0; q < 8; q++) {
            uint4 ha = P20[q], hb = P21[q];
            C0[0] = __hfma2(w2r[4*q+0], u2h2(ha.x), C0[0]);
            C0[1] = __hfma2(w2r[4*q+1], u2h2(ha.y), C0[1]);
            C0[2] = __hfma2(w2r[4*q+2], u2h2(ha.z), C0[2]);
            C0[3] = __hfma2(w2r[4*q+3], u2h2(ha.w), C0[3]);
            C1[0] = __hfma2(w2r[4*q+0], u2h2(hb.x), C1[0]);
            C1[1] = __hfma2(w2r[4*q+1], u2h2(hb.y), C1[1]);
            C1[2] = __hfma2(w2r[4*q+2], u2h2(hb.z), C1[2]);
            C1[3] = __hfma2(w2r[4*q+3], u2h2(hb.w), C1[3]);
        }

        float hd0, hd1;   // tail h outputs (only l2's final values used)

        if (s < T_STEPS) {        // layer 0, t = s
            LSTM_TAIL(0, A0, A1,
                      fmaf(wih0v, xs[0][s], bias0),
                      fmaf(wih0v, xs[1][s], bias0),
                      c00, c01, hd0, hd1)
        }
        if (s >= 1 && s <= T_STEPS) {   // layer 1, t = s-1
            LSTM_TAIL(1, B0, B1, bias1, bias1, c10, c11, hd0, hd1)
        }
        if (s >= 2) {                    // layer 2, t = s-2
            LSTM_TAIL(2, C0, C1, bias2, bias2, c20, c21, hd0, hd1)
            if (s == T_STEPS + 1 && type == 0) {
                h2last[0][j] = hd0;
                h2last[1][j] = hd1;
            }
        }
        __syncthreads();
    }

    // Fused FC: out[b0+r][e] = h2last[r] . fcW[e] + fcb[e]
    {
        const int r = tid >> 7, e = tid & 127;
        const float4* w4 = (const float4*)(fcW + e * HID);
        const float4* h4 = (const float4*)(h2last[r]);
        float acc = 0.f;
#pragma unroll
        for (int q = 0; q < 16; q++) {
            float4 a = w4[q], h = h4[q];
            acc = fmaf(a.x, h.x, acc);
            acc = fmaf(a.y, h.y, acc);
            acc = fmaf(a.z, h.z, acc);
            acc = fmaf(a.w, h.w, acc);
        }
        out[(size_t)(b0 + r) * EMBED + e] = acc + fcb[e];
    }
}

// ============================================================================
extern "C" void kernel_launch(void* const* d_in, const int* in_sizes, int n_in,
                              void* d_out, int out_size)
{
    const float* x    = (const float*)d_in[0];
    const float* Wih0 = (const float*)d_in[1];
    const float* Whh0 = (const float*)d_in[2];
    const float* bih0 = (const float*)d_in[3];
    const float* bhh0 = (const float*)d_in[4];
    const float* Wih1 = (const float*)d_in[5];
    const float* Whh1 = (const float*)d_in[6];
    const float* bih1 = (const float*)d_in[7];
    const float* bhh1 = (const float*)d_in[8];
    const float* Wih2 = (const float*)d_in[9];
    const float* Whh2 = (const float*)d_in[10];
    const float* bih2 = (const float*)d_in[11];
    const float* bhh2 = (const float*)d_in[12];
    const float* fcW  = (const float*)d_in[13];
    const float* fcb  = (const float*)d_in[14];

    lstm_all<<<BATCH / 2, 256>>>(x,
                                 Wih0, Whh0, bih0, bhh0,
                                 Wih1, Whh1, bih1, bhh1,
                                 Wih2, Whh2, bih2, bhh2,
                                 fcW, fcb, (float*)d_out);
}